// round 15
// baseline (speedup 1.0000x reference)
#include <cuda_runtime.h>
#include <math.h>

typedef unsigned long long ull;

#define BB 32
#define LL 128
#define WW 16
#define CEMB 64
#define NF 128
#define WEMB 256
#define EMB 384
#define HH 512
#define GG 2048
#define NT 4096
#define NCLS 17

#define CNN_SMEM ((128*193 + 8*16*64) * 4)

// LSTM smem: h permuted [32][516] + reduction slab [8 cells][4 gates][33]
#define HROW 516
#define REDW 132
#define LSTM_SMEM ((32 * HROW + 8 * REDW) * 4)

// ---------------- scratch (device globals: no allocation allowed) ----------
__device__ float g_X[NT * EMB];                       // [token=t*32+b][384]
__device__ float g_gx[(size_t)2 * LL * GG * BB];      // [dir][t][gate*512+cell][b]
__device__ float g_h2[2][2][512 * 32];                // ping-pong [buf][dir][cell][b]
__device__ float g_hall2[(size_t)LL * 1024 * BB];     // [t][dir*512+cell][b]
__device__ float g_z[(size_t)NT * 512];               // [token][512]
__device__ unsigned g_grpc[2][8];                     // monotonic group counters
__device__ unsigned g_rootc[2];                       // monotonic root counters
__device__ unsigned g_gen2[2];                        // published generation

// ---------------- helpers --------------------------------------------------
__device__ __forceinline__ void ffma2(ull& d, ull a, ull b) {
    asm("fma.rn.f32x2 %0, %1, %2, %0;" : "+l"(d) : "l"(a), "l"(b));
}
__device__ __forceinline__ ull mul2(ull a, ull b) {
    ull r; asm("mul.rn.f32x2 %0, %1, %2;" : "=l"(r) : "l"(a), "l"(b)); return r;
}
__device__ __forceinline__ ull dup2(float v) {
    unsigned u = __float_as_uint(v);
    return ((ull)u << 32) | (ull)u;
}
__device__ __forceinline__ ull pack2(float a, float b) {
    return ((ull)__float_as_uint(b) << 32) | (ull)__float_as_uint(a);
}
__device__ __forceinline__ float lo2(ull x) { return __uint_as_float((unsigned)x); }
__device__ __forceinline__ float hi2(ull x) { return __uint_as_float((unsigned)(x >> 32)); }

// fold: lanes with bit==0 end holding pair-sum of x, bit==1 pair-sum of y
__device__ __forceinline__ float foldf(float x, float y, int mask, bool bit) {
    float send = bit ? x : y;
    float keep = bit ? y : x;
    return keep + __shfl_xor_sync(0xffffffffu, send, mask);
}

// fast tanh via MUFU exp (rel err ~1e-7, vs 1e-3 budget)
__device__ __forceinline__ float tanh_fast(float x) {
    float e = __expf(2.0f * x);
    return 1.0f - 2.0f / (e + 1.0f);
}

// ---------------- two-level monotonic acq_rel tree barrier ------------------
// 64 arrivals/dir in 8 groups of 8. No fence (acq_rel chain), no nanosleep.
// All counters monotonic within a launch; init_kernel re-zeros per replay.
__device__ __forceinline__ void grid_sync_dir(int dir, int blk, unsigned target) {
    __syncthreads();                       // CTA-scope: all h writes drained
    if (threadIdx.x == 0) {
        unsigned* grp  = &g_grpc[dir][blk >> 3];
        unsigned* root = &g_rootc[dir];
        unsigned* gen  = &g_gen2[dir];
        unsigned ret;
        asm volatile("atom.add.acq_rel.gpu.global.u32 %0, [%1], 1;"
                     : "=r"(ret) : "l"(grp) : "memory");
        if (ret == target * 8u - 1u) {     // last in group this step
            unsigned r2;
            asm volatile("atom.add.acq_rel.gpu.global.u32 %0, [%1], 1;"
                         : "=r"(r2) : "l"(root) : "memory");
            if (r2 == target * 8u - 1u) {  // last group leader
                asm volatile("st.release.gpu.global.u32 [%0], %1;"
                             :: "l"(gen), "r"(target) : "memory");
            } else {
                unsigned g;
                do {
                    asm volatile("ld.acquire.gpu.global.u32 %0, [%1];"
                                 : "=r"(g) : "l"(gen) : "memory");
                } while (g < target);
            }
        } else {
            unsigned g;
            do {
                asm volatile("ld.acquire.gpu.global.u32 %0, [%1];"
                             : "=r"(g) : "l"(gen) : "memory");
            } while (g < target);
        }
    }
    __syncthreads();
}

// ---------------- init: zero h ping buffer + barrier state -----------------
__global__ void init_kernel() {
    int i = blockIdx.x * blockDim.x + threadIdx.x;
    if (i < 2) { g_rootc[i] = 0u; g_gen2[i] = 0u; }
    if (i < 16) g_grpc[i >> 3][i & 7] = 0u;
    if (i < 2 * 512 * 32) {
        g_h2[0][0][i] = 0.0f;   // buffer 0, both dirs (contiguous)
    }
}

// ---------------- word embedding gather -> X[:,128:384] --------------------
__global__ void embed_kernel(const int* __restrict__ wid,
                             const float* __restrict__ wemb) {
    int idx = blockIdx.x * blockDim.x + threadIdx.x;   // 4096*64
    int token = idx >> 6;
    int j = idx & 63;
    int l = token >> 5;
    int b = token & 31;
    int w = wid[b * LL + l];
    float4 v = *(const float4*)(wemb + (size_t)w * WEMB + j * 4);
    *(float4*)(g_X + (size_t)token * EMB + NF + j * 4) = v;
}

// ---------------- char CNN + relu + maxpool -> X[:,0:128] ------------------
__global__ void __launch_bounds__(256) cnn_kernel(const int* __restrict__ cid,
                                                  const float* __restrict__ cemb,
                                                  const float* __restrict__ cw,
                                                  const float* __restrict__ cb) {
    extern __shared__ float sm[];
    float* ws = sm;                 // [128][193] padded conv weights
    float* ce = sm + 128 * 193;     // [8][16][64] char embeddings
    int tid = threadIdx.x;

    for (int i = tid; i < NF * 192; i += 256)
        ws[(i / 192) * 193 + (i % 192)] = cw[i];

    int p0 = blockIdx.x * 8;        // p = b*128 + l
    for (int i = tid; i < 8 * WW * CEMB; i += 256) {
        int q = i >> 10;
        int w = (i >> 6) & 15;
        int c = i & 63;
        int id = cid[(p0 + q) * WW + w];
        ce[i] = cemb[id * CEMB + c];
    }
    __syncthreads();

    int f  = tid & 127;
    int qh = tid >> 7;
    float bias = cb[f];
    const float* wsf = ws + f * 193;

    for (int qq = 0; qq < 4; qq++) {
        int q = qh * 4 + qq;
        float acc[WW];
#pragma unroll
        for (int w = 0; w < WW; w++) acc[w] = bias;
        const float* cep = ce + q * (WW * CEMB);
        for (int c = 0; c < CEMB; c++) {
            float cr[WW];
#pragma unroll
            for (int w = 0; w < WW; w++) cr[w] = cep[w * CEMB + c];
            float k0 = wsf[c * 3 + 0];
            float k1 = wsf[c * 3 + 1];
            float k2 = wsf[c * 3 + 2];
#pragma unroll
            for (int w = 1; w < WW; w++)     acc[w] = fmaf(cr[w - 1], k0, acc[w]);
#pragma unroll
            for (int w = 0; w < WW; w++)     acc[w] = fmaf(cr[w],     k1, acc[w]);
#pragma unroll
            for (int w = 0; w < WW - 1; w++) acc[w] = fmaf(cr[w + 1], k2, acc[w]);
        }
        float m = 0.0f;
#pragma unroll
        for (int w = 0; w < WW; w++) m = fmaxf(m, acc[w]);
        int p = p0 + q;
        int bq = p >> 7;
        int lq = p & 127;
        g_X[(size_t)(lq * BB + bq) * EMB + f] = m;
    }
}

// ---------------- f32x2 128x128x16 SGEMM, double-buffered ------------------
template <int AMODE, int OMODE>
__global__ void __launch_bounds__(256, 2) sgemm2_kernel(const float* __restrict__ A,
                                                        const float* __restrict__ Bw,
                                                        const float* __restrict__ bias,
                                                        float* __restrict__ C,
                                                        int M, int N, int K) {
    __shared__ ull   Asd[2][16][130];   // dup-packed {a,a}
    __shared__ float Bs[2][16][132];
    int tid = threadIdx.x;
    int bm = blockIdx.y * 128;
    int bn = blockIdx.x * 128;
    int ty = tid >> 4, tx = tid & 15;

    int lr = tid >> 2;
    int lc = (tid & 3) * 4;
    const float* Bg0 = Bw + (size_t)(bn + lr) * K + lc;
    const float* Bg1 = Bw + (size_t)(bn + 64 + lr) * K + lc;

    const float* Ag0 = A;
    const float* Ag1 = A;
    int kk0 = 0, mg = 0, tA = 0, bA = 0;
    if (AMODE == 0) {
        Ag0 = A + (size_t)(bm + lr) * K + lc;
        Ag1 = A + (size_t)(bm + 64 + lr) * K + lc;
    } else {
        mg  = (tid & 31) * 4;
        kk0 = tid >> 5;
        tA  = (bm + mg) >> 5;
        bA  = (bm + mg) & 31;
    }

    ull acc[8][4];
#pragma unroll
    for (int i = 0; i < 8; i++)
#pragma unroll
        for (int q = 0; q < 4; q++) acc[i][q] = 0ull;

    int ntile = K >> 4;

    float4 a40, a41, b40, b41;
    b40 = *(const float4*)(Bg0);
    b41 = *(const float4*)(Bg1);
    if (AMODE == 0) {
        a40 = *(const float4*)(Ag0);
        a41 = *(const float4*)(Ag1);
    } else {
        a40 = *(const float4*)(A + ((size_t)tA * K + kk0) * 32 + bA);
        a41 = *(const float4*)(A + ((size_t)tA * K + kk0 + 8) * 32 + bA);
    }
    {
        Bs[0][lc + 0][lr] = b40.x; Bs[0][lc + 1][lr] = b40.y;
        Bs[0][lc + 2][lr] = b40.z; Bs[0][lc + 3][lr] = b40.w;
        Bs[0][lc + 0][64 + lr] = b41.x; Bs[0][lc + 1][64 + lr] = b41.y;
        Bs[0][lc + 2][64 + lr] = b41.z; Bs[0][lc + 3][64 + lr] = b41.w;
        if (AMODE == 0) {
            Asd[0][lc + 0][lr] = dup2(a40.x); Asd[0][lc + 1][lr] = dup2(a40.y);
            Asd[0][lc + 2][lr] = dup2(a40.z); Asd[0][lc + 3][lr] = dup2(a40.w);
            Asd[0][lc + 0][64 + lr] = dup2(a41.x); Asd[0][lc + 1][64 + lr] = dup2(a41.y);
            Asd[0][lc + 2][64 + lr] = dup2(a41.z); Asd[0][lc + 3][64 + lr] = dup2(a41.w);
        } else {
            Asd[0][kk0][mg + 0] = dup2(a40.x); Asd[0][kk0][mg + 1] = dup2(a40.y);
            Asd[0][kk0][mg + 2] = dup2(a40.z); Asd[0][kk0][mg + 3] = dup2(a40.w);
            Asd[0][kk0 + 8][mg + 0] = dup2(a41.x); Asd[0][kk0 + 8][mg + 1] = dup2(a41.y);
            Asd[0][kk0 + 8][mg + 2] = dup2(a41.z); Asd[0][kk0 + 8][mg + 3] = dup2(a41.w);
        }
    }
    __syncthreads();

    for (int it = 0; it < ntile; it++) {
        int cur = it & 1;
        int nxt = cur ^ 1;
        bool more = (it + 1) < ntile;
        if (more) {
            int k0 = (it + 1) * 16;
            b40 = *(const float4*)(Bg0 + k0);
            b41 = *(const float4*)(Bg1 + k0);
            if (AMODE == 0) {
                a40 = *(const float4*)(Ag0 + k0);
                a41 = *(const float4*)(Ag1 + k0);
            } else {
                a40 = *(const float4*)(A + ((size_t)tA * K + (k0 + kk0)) * 32 + bA);
                a41 = *(const float4*)(A + ((size_t)tA * K + (k0 + kk0 + 8)) * 32 + bA);
            }
        }
#pragma unroll
        for (int k = 0; k < 16; k++) {
            ull ar[8];
            ulonglong2 p0 = *(const ulonglong2*)&Asd[cur][k][ty * 8 + 0];
            ulonglong2 p1 = *(const ulonglong2*)&Asd[cur][k][ty * 8 + 2];
            ulonglong2 p2 = *(const ulonglong2*)&Asd[cur][k][ty * 8 + 4];
            ulonglong2 p3 = *(const ulonglong2*)&Asd[cur][k][ty * 8 + 6];
            ar[0] = p0.x; ar[1] = p0.y; ar[2] = p1.x; ar[3] = p1.y;
            ar[4] = p2.x; ar[5] = p2.y; ar[6] = p3.x; ar[7] = p3.y;
            ull br[4];
#pragma unroll
            for (int q = 0; q < 4; q++)
                br[q] = *(const ull*)&Bs[cur][k][2 * (q * 16 + tx)];
#pragma unroll
            for (int i = 0; i < 8; i++)
#pragma unroll
                for (int q = 0; q < 4; q++)
                    ffma2(acc[i][q], ar[i], br[q]);
        }
        if (more) {
            Bs[nxt][lc + 0][lr] = b40.x; Bs[nxt][lc + 1][lr] = b40.y;
            Bs[nxt][lc + 2][lr] = b40.z; Bs[nxt][lc + 3][lr] = b40.w;
            Bs[nxt][lc + 0][64 + lr] = b41.x; Bs[nxt][lc + 1][64 + lr] = b41.y;
            Bs[nxt][lc + 2][64 + lr] = b41.z; Bs[nxt][lc + 3][64 + lr] = b41.w;
            if (AMODE == 0) {
                Asd[nxt][lc + 0][lr] = dup2(a40.x); Asd[nxt][lc + 1][lr] = dup2(a40.y);
                Asd[nxt][lc + 2][lr] = dup2(a40.z); Asd[nxt][lc + 3][lr] = dup2(a40.w);
                Asd[nxt][lc + 0][64 + lr] = dup2(a41.x); Asd[nxt][lc + 1][64 + lr] = dup2(a41.y);
                Asd[nxt][lc + 2][64 + lr] = dup2(a41.z); Asd[nxt][lc + 3][64 + lr] = dup2(a41.w);
            } else {
                Asd[nxt][kk0][mg + 0] = dup2(a40.x); Asd[nxt][kk0][mg + 1] = dup2(a40.y);
                Asd[nxt][kk0][mg + 2] = dup2(a40.z); Asd[nxt][kk0][mg + 3] = dup2(a40.w);
                Asd[nxt][kk0 + 8][mg + 0] = dup2(a41.x); Asd[nxt][kk0 + 8][mg + 1] = dup2(a41.y);
                Asd[nxt][kk0 + 8][mg + 2] = dup2(a41.z); Asd[nxt][kk0 + 8][mg + 3] = dup2(a41.w);
            }
        }
        __syncthreads();
    }

#pragma unroll
    for (int i = 0; i < 8; i++) {
        int m = bm + ty * 8 + i;
#pragma unroll
        for (int q = 0; q < 4; q++) {
            int n0 = bn + 2 * (q * 16 + tx);
            float2 bv = *(const float2*)(bias + n0);
            float v0 = lo2(acc[i][q]) + bv.x;
            float v1 = hi2(acc[i][q]) + bv.y;
            if (OMODE == 0) {
                int t = m >> 5, b = m & 31;
                C[((size_t)t * N + n0) * 32 + b]       = v0;
                C[((size_t)t * N + n0 + 1) * 32 + b]   = v1;
            } else {
                if (v0 < 0.0f) v0 = expm1f(v0);
                if (v1 < 0.0f) v1 = expm1f(v1);
                *(float2*)(C + (size_t)m * N + n0) = make_float2(v0, v1);
            }
        }
    }
}

// ---------------- persistent BiLSTM: warp-pair per cell (batch split) ------
// 128 blocks (64/dir) x 512 threads. warp = (cell, half). Reg weights.
// Pair handoff via named barrier (bar.sync cell+1, 64) instead of block sync.
__global__ void __launch_bounds__(512) lstm_kernel(const float* __restrict__ whh_f,
                                                   const float* __restrict__ whh_b) {
    extern __shared__ float hs[];   // [32][516] then red [8 cells][4][33]
    float* red = hs + 32 * HROW;
    int tid = threadIdx.x;
    int dir = blockIdx.x >> 6;
    int blk = blockIdx.x & 63;
    int warp = tid >> 5;            // 0..15
    int lane = tid & 31;
    int cell = warp >> 1;           // 0..7
    int half = warp & 1;
    int cellg = blk * 8 + cell;     // global cell within dir
    const float* whh = dir ? whh_b : whh_f;

    // writer lane's (gate, b_local) per fold-tree landing pattern
    int w_gate = ((lane >> 4) & 1) + 2 * ((lane >> 3) & 1);   // 00->i 10->f 01->g 11->o
    int w_bl   = 2 * ((lane >> 1) & 1) + ((lane >> 2) & 1);
    bool w_own = (lane & 1) == 0;
    float* w_slot = red + cell * REDW + w_gate * 33;

    // ---- load weights into registers (both halves load identical copies)
    ull wr[32];
#pragma unroll
    for (int g = 0; g < 4; g++) {
        const float* row = whh + ((size_t)g * HH + cellg) * HH + lane * 16;
#pragma unroll
        for (int j = 0; j < 4; j++)
#pragma unroll
            for (int p = 0; p < 2; p++) {
                float w0 = __ldg(row + j * 4 + 2 * p);
                float w1 = __ldg(row + j * 4 + 2 * p + 1);
                wr[g * 8 + j * 2 + p] = pack2(w0, w1);
            }
    }

    float cst = 0.0f;

    for (int step = 0; step < LL; step++) {
        int t = dir ? (LL - 1 - step) : step;
        const float* hread = g_h2[step & 1][dir];
        float* hwrite = g_h2[(step & 1) ^ 1][dir];

        // ---- gx loads first: DRAM latency overlaps staging + syncthreads
        float gxi = 0.0f, gxf = 0.0f, gxg = 0.0f, gxo = 0.0f;
        if (half == 0) {
            const float* gxp = g_gx + ((size_t)dir * LL + t) * (size_t)(GG * BB);
            gxi = gxp[(0 * HH + cellg) * 32 + lane];
            gxf = gxp[(1 * HH + cellg) * 32 + lane];
            gxg = gxp[(2 * HH + cellg) * 32 + lane];
            gxo = gxp[(3 * HH + cellg) * 32 + lane];
        }

        // ---- stage h into permuted smem: 16 warps, each 32 c x 32 b
        {
            int b = lane;
#pragma unroll
            for (int pass = 0; pass < 8; pass++) {
                int c0 = warp * 32 + pass * 4;
                float v0 = hread[(c0 + 0) * 32 + b];
                float v1 = hread[(c0 + 1) * 32 + b];
                float v2 = hread[(c0 + 2) * 32 + b];
                float v3 = hread[(c0 + 3) * 32 + b];
                int j = (c0 >> 2) & 3;
                int l = c0 >> 4;
                *(float4*)(hs + b * HROW + j * 128 + l * 4) =
                    make_float4(v0, v1, v2, v3);
            }
        }
        __syncthreads();

#pragma unroll
        for (int bi = 0; bi < 4; bi++) {
            int batch = half * 4 + bi;
            float s[4][4];
#pragma unroll
            for (int bl = 0; bl < 4; bl++) {
                const float* rowp = hs + (batch * 4 + bl) * HROW + lane * 4;
                ulonglong2 h0 = *(const ulonglong2*)(rowp + 0);
                ulonglong2 h1 = *(const ulonglong2*)(rowp + 128);
                ulonglong2 h2 = *(const ulonglong2*)(rowp + 256);
                ulonglong2 h3 = *(const ulonglong2*)(rowp + 384);
                ull a0 = mul2(wr[0],  h0.x);
                ull a1 = mul2(wr[8],  h0.x);
                ull a2 = mul2(wr[16], h0.x);
                ull a3 = mul2(wr[24], h0.x);
                ffma2(a0, wr[1],  h0.y); ffma2(a1, wr[9],  h0.y);
                ffma2(a2, wr[17], h0.y); ffma2(a3, wr[25], h0.y);
                ffma2(a0, wr[2],  h1.x); ffma2(a1, wr[10], h1.x);
                ffma2(a2, wr[18], h1.x); ffma2(a3, wr[26], h1.x);
                ffma2(a0, wr[3],  h1.y); ffma2(a1, wr[11], h1.y);
                ffma2(a2, wr[19], h1.y); ffma2(a3, wr[27], h1.y);
                ffma2(a0, wr[4],  h2.x); ffma2(a1, wr[12], h2.x);
                ffma2(a2, wr[20], h2.x); ffma2(a3, wr[28], h2.x);
                ffma2(a0, wr[5],  h2.y); ffma2(a1, wr[13], h2.y);
                ffma2(a2, wr[21], h2.y); ffma2(a3, wr[29], h2.y);
                ffma2(a0, wr[6],  h3.x); ffma2(a1, wr[14], h3.x);
                ffma2(a2, wr[22], h3.x); ffma2(a3, wr[30], h3.x);
                ffma2(a0, wr[7],  h3.y); ffma2(a1, wr[15], h3.y);
                ffma2(a2, wr[23], h3.y); ffma2(a3, wr[31], h3.y);
                s[bl][0] = lo2(a0) + hi2(a0);
                s[bl][1] = lo2(a1) + hi2(a1);
                s[bl][2] = lo2(a2) + hi2(a2);
                s[bl][3] = lo2(a3) + hi2(a3);
            }
            // fold tree: gates onto bits {4,3}, b_local onto bits {1,2}
            bool b4 = (lane & 16) != 0;
            bool b3 = (lane & 8) != 0;
            bool b2f = (lane & 4) != 0;
            bool b1f = (lane & 2) != 0;
            float IF0 = foldf(s[0][0], s[0][1], 16, b4);
            float GO0 = foldf(s[0][2], s[0][3], 16, b4);
            float IF1 = foldf(s[1][0], s[1][1], 16, b4);
            float GO1 = foldf(s[1][2], s[1][3], 16, b4);
            float IF2 = foldf(s[2][0], s[2][1], 16, b4);
            float GO2 = foldf(s[2][2], s[2][3], 16, b4);
            float IF3 = foldf(s[3][0], s[3][1], 16, b4);
            float GO3 = foldf(s[3][2], s[3][3], 16, b4);
            float V0 = foldf(IF0, GO0, 8, b3);
            float V1 = foldf(IF1, GO1, 8, b3);
            float V2 = foldf(IF2, GO2, 8, b3);
            float V3 = foldf(IF3, GO3, 8, b3);
            float X = foldf(V0, V1, 4, b2f);
            float Y = foldf(V2, V3, 4, b2f);
            float Z = foldf(X, Y, 2, b1f);
            Z += __shfl_xor_sync(0xffffffffu, Z, 1);
            if (w_own) w_slot[batch * 4 + w_bl] = Z;
        }
        // pair handoff: only the 2 warps of this cell need to sync
        asm volatile("bar.sync %0, %1;" :: "r"(cell + 1), "r"(64) : "memory");

        // ---- activations for b = lane (half 0 owns epilogue)
        if (half == 0) {
            const float* rp = red + cell * REDW;
            float xi = rp[0 * 33 + lane] + gxi;
            float xf = rp[1 * 33 + lane] + gxf;
            float xg = rp[2 * 33 + lane] + gxg;
            float xo = rp[3 * 33 + lane] + gxo;

            float si = 1.0f / (1.0f + __expf(-xi));
            float sf = 1.0f / (1.0f + __expf(-xf));
            float so = 1.0f / (1.0f + __expf(-xo));
            float tg2 = tanh_fast(xg);
            cst = fmaf(sf, cst, si * tg2);
            float hn = so * tanh_fast(cst);

            hwrite[cellg * 32 + lane] = hn;
            g_hall2[((size_t)t * 1024 + dir * HH + cellg) * 32 + lane] = hn;
        }

        grid_sync_dir(dir, blk, (unsigned)(step + 1));
    }
}

// ---------------- head 2: out = z @ w2^T + b2 ------------------------------
__global__ void __launch_bounds__(256) head2_kernel(const float* __restrict__ w2,
                                                    const float* __restrict__ b2,
                                                    float* __restrict__ out) {
    int warp = (blockIdx.x * blockDim.x + threadIdx.x) >> 5;
    int lane = threadIdx.x & 31;
    if (warp >= NT) return;
    const float* z = g_z + (size_t)warp * 512;
    float zr[16];
#pragma unroll
    for (int i = 0; i < 16; i++) zr[i] = z[lane + 32 * i];
    int l = warp >> 5, b = warp & 31;
    float* op = out + ((size_t)b * LL + l) * NCLS;
    for (int cls = 0; cls < NCLS; cls++) {
        const float* wr = w2 + cls * 512;
        float s = 0.0f;
#pragma unroll
        for (int i = 0; i < 16; i++) s = fmaf(zr[i], wr[lane + 32 * i], s);
#pragma unroll
        for (int o = 16; o > 0; o >>= 1) s += __shfl_xor_sync(0xffffffffu, s, o);
        if (lane == 0) op[cls] = s + b2[cls];
    }
}

// ---------------- launcher -------------------------------------------------
extern "C" void kernel_launch(void* const* d_in, const int* in_sizes, int n_in,
                              void* d_out, int out_size) {
    (void)in_sizes; (void)n_in; (void)out_size;
    const int*   word_ids = (const int*)d_in[0];
    const int*   char_ids = (const int*)d_in[1];
    const float* char_emb = (const float*)d_in[3];
    const float* word_emb = (const float*)d_in[4];
    const float* conv_w   = (const float*)d_in[5];
    const float* conv_b   = (const float*)d_in[6];
    const float* w_ih_f   = (const float*)d_in[7];
    const float* w_hh_f   = (const float*)d_in[8];
    const float* b_f      = (const float*)d_in[9];
    const float* w_ih_b   = (const float*)d_in[10];
    const float* w_hh_b   = (const float*)d_in[11];
    const float* b_b      = (const float*)d_in[12];
    const float* w1       = (const float*)d_in[13];
    const float* b1       = (const float*)d_in[14];
    const float* w2       = (const float*)d_in[15];
    const float* b2       = (const float*)d_in[16];
    float* out = (float*)d_out;

    float *pX, *pGx, *pHall, *pZ;
    cudaGetSymbolAddress((void**)&pX,    g_X);
    cudaGetSymbolAddress((void**)&pGx,   g_gx);
    cudaGetSymbolAddress((void**)&pHall, g_hall2);
    cudaGetSymbolAddress((void**)&pZ,    g_z);

    cudaFuncSetAttribute(cnn_kernel,  cudaFuncAttributeMaxDynamicSharedMemorySize, CNN_SMEM);
    cudaFuncSetAttribute(lstm_kernel, cudaFuncAttributeMaxDynamicSharedMemorySize, LSTM_SMEM);

    init_kernel<<<128, 256>>>();
    embed_kernel<<<(NT * 64) / 256, 256>>>(word_ids, word_emb);
    cnn_kernel<<<512, 256, CNN_SMEM>>>(char_ids, char_emb, conv_w, conv_b);

    sgemm2_kernel<0, 0><<<dim3(GG / 128, NT / 128), 256>>>(pX, w_ih_f, b_f, pGx,
                                                           NT, GG, EMB);
    sgemm2_kernel<0, 0><<<dim3(GG / 128, NT / 128), 256>>>(pX, w_ih_b, b_b,
                                                           pGx + (size_t)LL * GG * BB,
                                                           NT, GG, EMB);

    lstm_kernel<<<128, 512, LSTM_SMEM>>>(w_hh_f, w_hh_b);

    sgemm2_kernel<1, 1><<<dim3(512 / 128, NT / 128), 256>>>(pHall, w1, b1, pZ,
                                                            NT, 512, 1024);
    head2_kernel<<<(NT * 32) / 256, 256>>>(w2, b2, out);
}

// round 16
// speedup vs baseline: 1.0780x; 1.0780x over previous
#include <cuda_runtime.h>
#include <math.h>

typedef unsigned long long ull;

#define BB 32
#define LL 128
#define WW 16
#define CEMB 64
#define NF 128
#define WEMB 256
#define EMB 384
#define HH 512
#define GG 2048
#define NT 4096
#define NCLS 17

#define CNN_SMEM ((128*193 + 8*16*64) * 4)

// LSTM smem: h permuted [32][516] + reduction slab [8 cells][4 gates][33]
#define HROW 516
#define REDW 132
#define LSTM_SMEM ((32 * HROW + 8 * REDW) * 4)

// ---------------- scratch (device globals: no allocation allowed) ----------
__device__ float g_X[NT * EMB];                       // [token=t*32+b][384]
__device__ float g_gx[(size_t)2 * LL * GG * BB];      // [dir][t][gate*512+cell][b]
__device__ float g_h2[2][2][512 * 32];                // ping-pong [buf][dir][cell][b]
__device__ float g_hall2[(size_t)LL * 1024 * BB];     // [t][dir*512+cell][b]
__device__ float g_z[(size_t)NT * 512];               // [token][512]
__device__ unsigned g_cnt2[2];                        // monotonic arrival counters
__device__ unsigned g_gen2[2];                        // published generation

// ---------------- helpers --------------------------------------------------
__device__ __forceinline__ void ffma2(ull& d, ull a, ull b) {
    asm("fma.rn.f32x2 %0, %1, %2, %0;" : "+l"(d) : "l"(a), "l"(b));
}
__device__ __forceinline__ ull mul2(ull a, ull b) {
    ull r; asm("mul.rn.f32x2 %0, %1, %2;" : "=l"(r) : "l"(a), "l"(b)); return r;
}
__device__ __forceinline__ ull dup2(float v) {
    unsigned u = __float_as_uint(v);
    return ((ull)u << 32) | (ull)u;
}
__device__ __forceinline__ ull pack2(float a, float b) {
    return ((ull)__float_as_uint(b) << 32) | (ull)__float_as_uint(a);
}
__device__ __forceinline__ float lo2(ull x) { return __uint_as_float((unsigned)x); }
__device__ __forceinline__ float hi2(ull x) { return __uint_as_float((unsigned)(x >> 32)); }

// fold: lanes with bit==0 end holding pair-sum of x, bit==1 pair-sum of y
__device__ __forceinline__ float foldf(float x, float y, int mask, bool bit) {
    float send = bit ? x : y;
    float keep = bit ? y : x;
    return keep + __shfl_xor_sync(0xffffffffu, send, mask);
}

// fast tanh via MUFU exp (rel err ~1e-7, vs 1e-3 budget)
__device__ __forceinline__ float tanh_fast(float x) {
    float e = __expf(2.0f * x);
    return 1.0f - 2.0f / (e + 1.0f);
}

// ---------------- flat monotonic acquire/release grid barrier (R14) --------
// 64 arrivals per direction. No threadfence (no CCTL.IVALL), no nanosleep.
// Counter/gen are monotonic within a launch; init_kernel re-zeros per replay.
__device__ __forceinline__ void grid_sync_dir(int dir, unsigned target) {
    __syncthreads();                       // all warps' h writes done (CTA scope)
    if (threadIdx.x == 0) {
        unsigned* cnt = &g_cnt2[dir];
        unsigned* gen = &g_gen2[dir];
        unsigned ret;
        asm volatile("atom.add.acq_rel.gpu.global.u32 %0, [%1], 1;"
                     : "=r"(ret) : "l"(cnt) : "memory");
        if (ret == target * 64u - 1u) {
            asm volatile("st.release.gpu.global.u32 [%0], %1;"
                         :: "l"(gen), "r"(target) : "memory");
        } else {
            unsigned g;
            do {
                asm volatile("ld.acquire.gpu.global.u32 %0, [%1];"
                             : "=r"(g) : "l"(gen) : "memory");
            } while (g < target);
        }
    }
    __syncthreads();
}

// ---------------- init: zero h ping buffer + barrier state -----------------
__global__ void init_kernel() {
    int i = blockIdx.x * blockDim.x + threadIdx.x;
    if (i < 2) { g_cnt2[i] = 0u; g_gen2[i] = 0u; }
    if (i < 2 * 512 * 32) {
        g_h2[0][0][i] = 0.0f;   // buffer 0, both dirs (contiguous)
    }
}

// ---------------- word embedding gather -> X[:,128:384] --------------------
__global__ void embed_kernel(const int* __restrict__ wid,
                             const float* __restrict__ wemb) {
    int idx = blockIdx.x * blockDim.x + threadIdx.x;   // 4096*64
    int token = idx >> 6;
    int j = idx & 63;
    int l = token >> 5;
    int b = token & 31;
    int w = wid[b * LL + l];
    float4 v = *(const float4*)(wemb + (size_t)w * WEMB + j * 4);
    *(float4*)(g_X + (size_t)token * EMB + NF + j * 4) = v;
}

// ---------------- char CNN + relu + maxpool -> X[:,0:128] ------------------
__global__ void __launch_bounds__(256) cnn_kernel(const int* __restrict__ cid,
                                                  const float* __restrict__ cemb,
                                                  const float* __restrict__ cw,
                                                  const float* __restrict__ cb) {
    extern __shared__ float sm[];
    float* ws = sm;                 // [128][193] padded conv weights
    float* ce = sm + 128 * 193;     // [8][16][64] char embeddings
    int tid = threadIdx.x;

    for (int i = tid; i < NF * 192; i += 256)
        ws[(i / 192) * 193 + (i % 192)] = cw[i];

    int p0 = blockIdx.x * 8;        // p = b*128 + l
    for (int i = tid; i < 8 * WW * CEMB; i += 256) {
        int q = i >> 10;
        int w = (i >> 6) & 15;
        int c = i & 63;
        int id = cid[(p0 + q) * WW + w];
        ce[i] = cemb[id * CEMB + c];
    }
    __syncthreads();

    int f  = tid & 127;
    int qh = tid >> 7;
    float bias = cb[f];
    const float* wsf = ws + f * 193;

    for (int qq = 0; qq < 4; qq++) {
        int q = qh * 4 + qq;
        float acc[WW];
#pragma unroll
        for (int w = 0; w < WW; w++) acc[w] = bias;
        const float* cep = ce + q * (WW * CEMB);
        for (int c = 0; c < CEMB; c++) {
            float cr[WW];
#pragma unroll
            for (int w = 0; w < WW; w++) cr[w] = cep[w * CEMB + c];
            float k0 = wsf[c * 3 + 0];
            float k1 = wsf[c * 3 + 1];
            float k2 = wsf[c * 3 + 2];
#pragma unroll
            for (int w = 1; w < WW; w++)     acc[w] = fmaf(cr[w - 1], k0, acc[w]);
#pragma unroll
            for (int w = 0; w < WW; w++)     acc[w] = fmaf(cr[w],     k1, acc[w]);
#pragma unroll
            for (int w = 0; w < WW - 1; w++) acc[w] = fmaf(cr[w + 1], k2, acc[w]);
        }
        float m = 0.0f;
#pragma unroll
        for (int w = 0; w < WW; w++) m = fmaxf(m, acc[w]);
        int p = p0 + q;
        int bq = p >> 7;
        int lq = p & 127;
        g_X[(size_t)(lq * BB + bq) * EMB + f] = m;
    }
}

// ---------------- f32x2 128x128x16 SGEMM, double-buffered ------------------
// blockIdx.z selects (Bw,bias,C) vs (Bw2,bias2,C + CZOFF) for merged launches.
template <int AMODE, int OMODE>
__global__ void __launch_bounds__(256, 2) sgemm2_kernel(const float* __restrict__ A,
                                                        const float* __restrict__ Bw,
                                                        const float* __restrict__ bias,
                                                        float* __restrict__ C,
                                                        const float* __restrict__ Bw2,
                                                        const float* __restrict__ bias2,
                                                        size_t czoff,
                                                        int M, int N, int K) {
    if (blockIdx.z) { Bw = Bw2; bias = bias2; C += czoff; }
    __shared__ ull   Asd[2][16][130];   // dup-packed {a,a}
    __shared__ float Bs[2][16][132];
    int tid = threadIdx.x;
    int bm = blockIdx.y * 128;
    int bn = blockIdx.x * 128;
    int ty = tid >> 4, tx = tid & 15;

    int lr = tid >> 2;
    int lc = (tid & 3) * 4;
    const float* Bg0 = Bw + (size_t)(bn + lr) * K + lc;
    const float* Bg1 = Bw + (size_t)(bn + 64 + lr) * K + lc;

    const float* Ag0 = A;
    const float* Ag1 = A;
    int kk0 = 0, mg = 0, tA = 0, bA = 0;
    if (AMODE == 0) {
        Ag0 = A + (size_t)(bm + lr) * K + lc;
        Ag1 = A + (size_t)(bm + 64 + lr) * K + lc;
    } else {
        mg  = (tid & 31) * 4;
        kk0 = tid >> 5;
        tA  = (bm + mg) >> 5;
        bA  = (bm + mg) & 31;
    }

    ull acc[8][4];
#pragma unroll
    for (int i = 0; i < 8; i++)
#pragma unroll
        for (int q = 0; q < 4; q++) acc[i][q] = 0ull;

    int ntile = K >> 4;

    float4 a40, a41, b40, b41;
    b40 = *(const float4*)(Bg0);
    b41 = *(const float4*)(Bg1);
    if (AMODE == 0) {
        a40 = *(const float4*)(Ag0);
        a41 = *(const float4*)(Ag1);
    } else {
        a40 = *(const float4*)(A + ((size_t)tA * K + kk0) * 32 + bA);
        a41 = *(const float4*)(A + ((size_t)tA * K + kk0 + 8) * 32 + bA);
    }
    {
        Bs[0][lc + 0][lr] = b40.x; Bs[0][lc + 1][lr] = b40.y;
        Bs[0][lc + 2][lr] = b40.z; Bs[0][lc + 3][lr] = b40.w;
        Bs[0][lc + 0][64 + lr] = b41.x; Bs[0][lc + 1][64 + lr] = b41.y;
        Bs[0][lc + 2][64 + lr] = b41.z; Bs[0][lc + 3][64 + lr] = b41.w;
        if (AMODE == 0) {
            Asd[0][lc + 0][lr] = dup2(a40.x); Asd[0][lc + 1][lr] = dup2(a40.y);
            Asd[0][lc + 2][lr] = dup2(a40.z); Asd[0][lc + 3][lr] = dup2(a40.w);
            Asd[0][lc + 0][64 + lr] = dup2(a41.x); Asd[0][lc + 1][64 + lr] = dup2(a41.y);
            Asd[0][lc + 2][64 + lr] = dup2(a41.z); Asd[0][lc + 3][64 + lr] = dup2(a41.w);
        } else {
            Asd[0][kk0][mg + 0] = dup2(a40.x); Asd[0][kk0][mg + 1] = dup2(a40.y);
            Asd[0][kk0][mg + 2] = dup2(a40.z); Asd[0][kk0][mg + 3] = dup2(a40.w);
            Asd[0][kk0 + 8][mg + 0] = dup2(a41.x); Asd[0][kk0 + 8][mg + 1] = dup2(a41.y);
            Asd[0][kk0 + 8][mg + 2] = dup2(a41.z); Asd[0][kk0 + 8][mg + 3] = dup2(a41.w);
        }
    }
    __syncthreads();

    for (int it = 0; it < ntile; it++) {
        int cur = it & 1;
        int nxt = cur ^ 1;
        bool more = (it + 1) < ntile;
        if (more) {
            int k0 = (it + 1) * 16;
            b40 = *(const float4*)(Bg0 + k0);
            b41 = *(const float4*)(Bg1 + k0);
            if (AMODE == 0) {
                a40 = *(const float4*)(Ag0 + k0);
                a41 = *(const float4*)(Ag1 + k0);
            } else {
                a40 = *(const float4*)(A + ((size_t)tA * K + (k0 + kk0)) * 32 + bA);
                a41 = *(const float4*)(A + ((size_t)tA * K + (k0 + kk0 + 8)) * 32 + bA);
            }
        }
#pragma unroll
        for (int k = 0; k < 16; k++) {
            ull ar[8];
            ulonglong2 p0 = *(const ulonglong2*)&Asd[cur][k][ty * 8 + 0];
            ulonglong2 p1 = *(const ulonglong2*)&Asd[cur][k][ty * 8 + 2];
            ulonglong2 p2 = *(const ulonglong2*)&Asd[cur][k][ty * 8 + 4];
            ulonglong2 p3 = *(const ulonglong2*)&Asd[cur][k][ty * 8 + 6];
            ar[0] = p0.x; ar[1] = p0.y; ar[2] = p1.x; ar[3] = p1.y;
            ar[4] = p2.x; ar[5] = p2.y; ar[6] = p3.x; ar[7] = p3.y;
            ull br[4];
#pragma unroll
            for (int q = 0; q < 4; q++)
                br[q] = *(const ull*)&Bs[cur][k][2 * (q * 16 + tx)];
#pragma unroll
            for (int i = 0; i < 8; i++)
#pragma unroll
                for (int q = 0; q < 4; q++)
                    ffma2(acc[i][q], ar[i], br[q]);
        }
        if (more) {
            Bs[nxt][lc + 0][lr] = b40.x; Bs[nxt][lc + 1][lr] = b40.y;
            Bs[nxt][lc + 2][lr] = b40.z; Bs[nxt][lc + 3][lr] = b40.w;
            Bs[nxt][lc + 0][64 + lr] = b41.x; Bs[nxt][lc + 1][64 + lr] = b41.y;
            Bs[nxt][lc + 2][64 + lr] = b41.z; Bs[nxt][lc + 3][64 + lr] = b41.w;
            if (AMODE == 0) {
                Asd[nxt][lc + 0][lr] = dup2(a40.x); Asd[nxt][lc + 1][lr] = dup2(a40.y);
                Asd[nxt][lc + 2][lr] = dup2(a40.z); Asd[nxt][lc + 3][lr] = dup2(a40.w);
                Asd[nxt][lc + 0][64 + lr] = dup2(a41.x); Asd[nxt][lc + 1][64 + lr] = dup2(a41.y);
                Asd[nxt][lc + 2][64 + lr] = dup2(a41.z); Asd[nxt][lc + 3][64 + lr] = dup2(a41.w);
            } else {
                Asd[nxt][kk0][mg + 0] = dup2(a40.x); Asd[nxt][kk0][mg + 1] = dup2(a40.y);
                Asd[nxt][kk0][mg + 2] = dup2(a40.z); Asd[nxt][kk0][mg + 3] = dup2(a40.w);
                Asd[nxt][kk0 + 8][mg + 0] = dup2(a41.x); Asd[nxt][kk0 + 8][mg + 1] = dup2(a41.y);
                Asd[nxt][kk0 + 8][mg + 2] = dup2(a41.z); Asd[nxt][kk0 + 8][mg + 3] = dup2(a41.w);
            }
        }
        __syncthreads();
    }

#pragma unroll
    for (int i = 0; i < 8; i++) {
        int m = bm + ty * 8 + i;
#pragma unroll
        for (int q = 0; q < 4; q++) {
            int n0 = bn + 2 * (q * 16 + tx);
            float2 bv = *(const float2*)(bias + n0);
            float v0 = lo2(acc[i][q]) + bv.x;
            float v1 = hi2(acc[i][q]) + bv.y;
            if (OMODE == 0) {
                int t = m >> 5, b = m & 31;
                C[((size_t)t * N + n0) * 32 + b]       = v0;
                C[((size_t)t * N + n0 + 1) * 32 + b]   = v1;
            } else {
                if (v0 < 0.0f) v0 = expm1f(v0);
                if (v1 < 0.0f) v1 = expm1f(v1);
                *(float2*)(C + (size_t)m * N + n0) = make_float2(v0, v1);
            }
        }
    }
}

// ---------------- persistent BiLSTM (R14 + cross-barrier gx prefetch) ------
// 128 blocks (64/dir) x 512 threads. warp = (cell, half). Reg weights.
__global__ void __launch_bounds__(512) lstm_kernel(const float* __restrict__ whh_f,
                                                   const float* __restrict__ whh_b) {
    extern __shared__ float hs[];   // [32][516] then red [8 cells][4][33]
    float* red = hs + 32 * HROW;
    int tid = threadIdx.x;
    int dir = blockIdx.x >> 6;
    int blk = blockIdx.x & 63;
    (void)blk;
    int warp = tid >> 5;            // 0..15
    int lane = tid & 31;
    int cell = warp >> 1;           // 0..7
    int half = warp & 1;
    int cellg = (blockIdx.x & 63) * 8 + cell;   // global cell within dir
    const float* whh = dir ? whh_b : whh_f;

    // writer lane's (gate, b_local) per fold-tree landing pattern
    int w_gate = ((lane >> 4) & 1) + 2 * ((lane >> 3) & 1);   // 00->i 10->f 01->g 11->o
    int w_bl   = 2 * ((lane >> 1) & 1) + ((lane >> 2) & 1);
    bool w_own = (lane & 1) == 0;
    float* w_slot = red + cell * REDW + w_gate * 33;

    // ---- load weights into registers (both halves load identical copies)
    ull wr[32];
#pragma unroll
    for (int g = 0; g < 4; g++) {
        const float* row = whh + ((size_t)g * HH + cellg) * HH + lane * 16;
#pragma unroll
        for (int j = 0; j < 4; j++)
#pragma unroll
            for (int p = 0; p < 2; p++) {
                float w0 = __ldg(row + j * 4 + 2 * p);
                float w1 = __ldg(row + j * 4 + 2 * p + 1);
                wr[g * 8 + j * 2 + p] = pack2(w0, w1);
            }
    }

    float cst = 0.0f;

    // ---- prefetch gx for step 0
    const float* gxbase = g_gx + (size_t)dir * LL * (size_t)(GG * BB);
    float gxi = 0.0f, gxf = 0.0f, gxg = 0.0f, gxo = 0.0f;
    if (half == 0) {
        int t0 = dir ? (LL - 1) : 0;
        const float* gx0 = gxbase + (size_t)t0 * (GG * BB);
        gxi = gx0[(0 * HH + cellg) * 32 + lane];
        gxf = gx0[(1 * HH + cellg) * 32 + lane];
        gxg = gx0[(2 * HH + cellg) * 32 + lane];
        gxo = gx0[(3 * HH + cellg) * 32 + lane];
    }

    for (int step = 0; step < LL; step++) {
        int t = dir ? (LL - 1 - step) : step;
        const float* hread = g_h2[step & 1][dir];
        float* hwrite = g_h2[(step & 1) ^ 1][dir];

        // ---- stage h into permuted smem: 16 warps, each 32 c x 32 b
        {
            int b = lane;
#pragma unroll
            for (int pass = 0; pass < 8; pass++) {
                int c0 = warp * 32 + pass * 4;
                float v0 = hread[(c0 + 0) * 32 + b];
                float v1 = hread[(c0 + 1) * 32 + b];
                float v2 = hread[(c0 + 2) * 32 + b];
                float v3 = hread[(c0 + 3) * 32 + b];
                int j = (c0 >> 2) & 3;
                int l = c0 >> 4;
                *(float4*)(hs + b * HROW + j * 128 + l * 4) =
                    make_float4(v0, v1, v2, v3);
            }
        }
        __syncthreads();

#pragma unroll
        for (int bi = 0; bi < 4; bi++) {
            int batch = half * 4 + bi;
            float s[4][4];
#pragma unroll
            for (int bl = 0; bl < 4; bl++) {
                const float* rowp = hs + (batch * 4 + bl) * HROW + lane * 4;
                ulonglong2 h0 = *(const ulonglong2*)(rowp + 0);
                ulonglong2 h1 = *(const ulonglong2*)(rowp + 128);
                ulonglong2 h2 = *(const ulonglong2*)(rowp + 256);
                ulonglong2 h3 = *(const ulonglong2*)(rowp + 384);
                ull a0 = mul2(wr[0],  h0.x);
                ull a1 = mul2(wr[8],  h0.x);
                ull a2 = mul2(wr[16], h0.x);
                ull a3 = mul2(wr[24], h0.x);
                ffma2(a0, wr[1],  h0.y); ffma2(a1, wr[9],  h0.y);
                ffma2(a2, wr[17], h0.y); ffma2(a3, wr[25], h0.y);
                ffma2(a0, wr[2],  h1.x); ffma2(a1, wr[10], h1.x);
                ffma2(a2, wr[18], h1.x); ffma2(a3, wr[26], h1.x);
                ffma2(a0, wr[3],  h1.y); ffma2(a1, wr[11], h1.y);
                ffma2(a2, wr[19], h1.y); ffma2(a3, wr[27], h1.y);
                ffma2(a0, wr[4],  h2.x); ffma2(a1, wr[12], h2.x);
                ffma2(a2, wr[20], h2.x); ffma2(a3, wr[28], h2.x);
                ffma2(a0, wr[5],  h2.y); ffma2(a1, wr[13], h2.y);
                ffma2(a2, wr[21], h2.y); ffma2(a3, wr[29], h2.y);
                ffma2(a0, wr[6],  h3.x); ffma2(a1, wr[14], h3.x);
                ffma2(a2, wr[22], h3.x); ffma2(a3, wr[30], h3.x);
                ffma2(a0, wr[7],  h3.y); ffma2(a1, wr[15], h3.y);
                ffma2(a2, wr[23], h3.y); ffma2(a3, wr[31], h3.y);
                s[bl][0] = lo2(a0) + hi2(a0);
                s[bl][1] = lo2(a1) + hi2(a1);
                s[bl][2] = lo2(a2) + hi2(a2);
                s[bl][3] = lo2(a3) + hi2(a3);
            }
            // fold tree: gates onto bits {4,3}, b_local onto bits {1,2}
            bool b4 = (lane & 16) != 0;
            bool b3 = (lane & 8) != 0;
            bool b2f = (lane & 4) != 0;
            bool b1f = (lane & 2) != 0;
            float IF0 = foldf(s[0][0], s[0][1], 16, b4);
            float GO0 = foldf(s[0][2], s[0][3], 16, b4);
            float IF1 = foldf(s[1][0], s[1][1], 16, b4);
            float GO1 = foldf(s[1][2], s[1][3], 16, b4);
            float IF2 = foldf(s[2][0], s[2][1], 16, b4);
            float GO2 = foldf(s[2][2], s[2][3], 16, b4);
            float IF3 = foldf(s[3][0], s[3][1], 16, b4);
            float GO3 = foldf(s[3][2], s[3][3], 16, b4);
            float V0 = foldf(IF0, GO0, 8, b3);
            float V1 = foldf(IF1, GO1, 8, b3);
            float V2 = foldf(IF2, GO2, 8, b3);
            float V3 = foldf(IF3, GO3, 8, b3);
            float X = foldf(V0, V1, 4, b2f);
            float Y = foldf(V2, V3, 4, b2f);
            float Z = foldf(X, Y, 2, b1f);
            Z += __shfl_xor_sync(0xffffffffu, Z, 1);
            if (w_own) w_slot[batch * 4 + w_bl] = Z;
        }
        __syncthreads();      // pair's fold results visible

        // ---- activations for b = lane (half 0 owns epilogue)
        if (half == 0) {
            const float* rp = red + cell * REDW;
            float xi = rp[0 * 33 + lane] + gxi;
            float xf = rp[1 * 33 + lane] + gxf;
            float xg = rp[2 * 33 + lane] + gxg;
            float xo = rp[3 * 33 + lane] + gxo;

            float si = 1.0f / (1.0f + __expf(-xi));
            float sf = 1.0f / (1.0f + __expf(-xf));
            float so = 1.0f / (1.0f + __expf(-xo));
            float tg2 = tanh_fast(xg);
            cst = fmaf(sf, cst, si * tg2);
            float hn = so * tanh_fast(cst);

            hwrite[cellg * 32 + lane] = hn;
            g_hall2[((size_t)t * 1024 + dir * HH + cellg) * 32 + lane] = hn;
        }

        // ---- prefetch next step's gx BEFORE the barrier (hidden under it)
        if (half == 0 && step + 1 < LL) {
            int tn = dir ? (LL - 2 - step) : (step + 1);
            const float* gxn = gxbase + (size_t)tn * (GG * BB);
            gxi = gxn[(0 * HH + cellg) * 32 + lane];
            gxf = gxn[(1 * HH + cellg) * 32 + lane];
            gxg = gxn[(2 * HH + cellg) * 32 + lane];
            gxo = gxn[(3 * HH + cellg) * 32 + lane];
        }

        grid_sync_dir(dir, (unsigned)(step + 1));
    }
}

// ---------------- head 2: out = z @ w2^T + b2 ------------------------------
__global__ void __launch_bounds__(256) head2_kernel(const float* __restrict__ w2,
                                                    const float* __restrict__ b2,
                                                    float* __restrict__ out) {
    int warp = (blockIdx.x * blockDim.x + threadIdx.x) >> 5;
    int lane = threadIdx.x & 31;
    if (warp >= NT) return;
    const float* z = g_z + (size_t)warp * 512;
    float zr[16];
#pragma unroll
    for (int i = 0; i < 16; i++) zr[i] = z[lane + 32 * i];
    int l = warp >> 5, b = warp & 31;
    float* op = out + ((size_t)b * LL + l) * NCLS;
    for (int cls = 0; cls < NCLS; cls++) {
        const float* wr = w2 + cls * 512;
        float s = 0.0f;
#pragma unroll
        for (int i = 0; i < 16; i++) s = fmaf(zr[i], wr[lane + 32 * i], s);
#pragma unroll
        for (int o = 16; o > 0; o >>= 1) s += __shfl_xor_sync(0xffffffffu, s, o);
        if (lane == 0) op[cls] = s + b2[cls];
    }
}

// ---------------- launcher -------------------------------------------------
extern "C" void kernel_launch(void* const* d_in, const int* in_sizes, int n_in,
                              void* d_out, int out_size) {
    (void)in_sizes; (void)n_in; (void)out_size;
    const int*   word_ids = (const int*)d_in[0];
    const int*   char_ids = (const int*)d_in[1];
    const float* char_emb = (const float*)d_in[3];
    const float* word_emb = (const float*)d_in[4];
    const float* conv_w   = (const float*)d_in[5];
    const float* conv_b   = (const float*)d_in[6];
    const float* w_ih_f   = (const float*)d_in[7];
    const float* w_hh_f   = (const float*)d_in[8];
    const float* b_f      = (const float*)d_in[9];
    const float* w_ih_b   = (const float*)d_in[10];
    const float* w_hh_b   = (const float*)d_in[11];
    const float* b_b      = (const float*)d_in[12];
    const float* w1       = (const float*)d_in[13];
    const float* b1       = (const float*)d_in[14];
    const float* w2       = (const float*)d_in[15];
    const float* b2       = (const float*)d_in[16];
    float* out = (float*)d_out;

    float *pX, *pGx, *pHall, *pZ;
    cudaGetSymbolAddress((void**)&pX,    g_X);
    cudaGetSymbolAddress((void**)&pGx,   g_gx);
    cudaGetSymbolAddress((void**)&pHall, g_hall2);
    cudaGetSymbolAddress((void**)&pZ,    g_z);

    cudaFuncSetAttribute(cnn_kernel,  cudaFuncAttributeMaxDynamicSharedMemorySize, CNN_SMEM);
    cudaFuncSetAttribute(lstm_kernel, cudaFuncAttributeMaxDynamicSharedMemorySize, LSTM_SMEM);

    init_kernel<<<128, 256>>>();
    embed_kernel<<<(NT * 64) / 256, 256>>>(word_ids, word_emb);
    cnn_kernel<<<512, 256, CNN_SMEM>>>(char_ids, char_emb, conv_w, conv_b);

    // merged gx GEMMs: z=0 -> forward dir, z=1 -> backward dir
    sgemm2_kernel<0, 0><<<dim3(GG / 128, NT / 128, 2), 256>>>(
        pX, w_ih_f, b_f, pGx, w_ih_b, b_b, (size_t)LL * GG * BB,
        NT, GG, EMB);

    lstm_kernel<<<128, 512, LSTM_SMEM>>>(w_hh_f, w_hh_b);

    sgemm2_kernel<1, 1><<<dim3(512 / 128, NT / 128, 1), 256>>>(
        pHall, w1, b1, pZ, w1, b1, 0,
        NT, 512, 1024);
    head2_kernel<<<(NT * 32) / 256, 256>>>(w2, b2, out);
}